// round 5
// baseline (speedup 1.0000x reference)
#include <cuda_runtime.h>
#include <cuda_bf16.h>
#include <stdint.h>

// FractionalSTFT — exact-identity reduction (verified: rel_err 2.7e-7):
//   Uniform 16384-point fractional-frequency lattice => W^H W = 16 I =>
//   pinv(W) W = I; encode->extend->decode is the per-frame identity; Hann
//   OLA / win_norm reconstructs xp exactly; crop returns x verbatim.
//   Output == input, so the task is one 2MiB D2D move (4MiB LTS traffic,
//   ~0.7us warm at the ~6.3TB/s LTS cap).
//
// R4: driver memcpy node = 4.64us end-to-end. This round: tuned copy kernel
// to test whether the residual above the ~0.7us data floor is node dispatch
// (then this is neutral) or driver-copy inefficiency (then this wins).
//   - 4x float4 per thread, loads batched before stores (MLP=4)
//   - 128 blocks x 256 threads = exactly one wave, zero tail for n4=131072

__global__ __launch_bounds__(256)
void fstft_copy4(const float4* __restrict__ src, float4* __restrict__ dst,
                 int n4) {
    int base = (blockIdx.x * 256 + threadIdx.x) * 4;
    if (base + 3 < n4) {
        // Batch 4 independent LDG.128 before any STG: MLP=4.
        float4 a = src[base + 0];
        float4 b = src[base + 1];
        float4 c = src[base + 2];
        float4 d = src[base + 3];
        dst[base + 0] = a;
        dst[base + 1] = b;
        dst[base + 2] = c;
        dst[base + 3] = d;
    } else {
        for (int i = base; i < n4; ++i) dst[i] = src[i];
    }
}

extern "C" void kernel_launch(void* const* d_in, const int* in_sizes, int n_in,
                              void* d_out, int out_size) {
    const float* x = (const float*)d_in[0];   // (2,2,131072) float32
    float* out = (float*)d_out;

    int n4 = out_size / 4;                    // 131072 float4
    int blocks = (n4 + 256 * 4 - 1) / (256 * 4);   // 128 for this shape
    fstft_copy4<<<blocks, 256>>>((const float4*)x, (float4*)out, n4);

    int tail = out_size - n4 * 4;             // 0 for this shape; defensive
    if (tail > 0) {
        cudaMemcpyAsync(out + n4 * 4, x + n4 * 4, tail * sizeof(float),
                        cudaMemcpyDeviceToDevice);
    }
}

// round 6
// speedup vs baseline: 1.0561x; 1.0561x over previous
#include <cuda_runtime.h>
#include <cuda_bf16.h>
#include <stdint.h>

// FractionalSTFT — exact-identity reduction (verified across R3-R5:
// rel_err 2.740721e-07 on every variant):
//   The k2 grid is the uniform 16384-point fractional-frequency lattice
//   (step 1/16 over the full circle), so W^H W = 16 I and pinv(W) W = I.
//   Encode -> Hermitian-extend -> decode is the identity on each frame;
//   Hann overlap-add / win_norm reconstructs the padded signal exactly and
//   the crop returns x verbatim. Output == input: the task is one 2 MiB
//   device-to-device move.
//
// Measured landscape (GB300, graph-replay timing):
//   - driver memcpy node:            4.64 us   <- floor
//   - naive copy kernel (R3):        6.88 us
//   - tuned MLP=4 copy kernel (R5):  6.62 us
// Kernel content is irrelevant (ncu cold times ~equal); a user-kernel graph
// node costs ~2 us more per replay than a memcpy node. Data floor is
// ~0.7 us (4 MiB LTS traffic warm); the rest is fixed replay overhead.
// => The driver memcpy node is the optimum. Reverting to it.

extern "C" void kernel_launch(void* const* d_in, const int* in_sizes, int n_in,
                              void* d_out, int out_size) {
    const float* x = (const float*)d_in[0];   // (2,2,131072) float32
    float* out = (float*)d_out;

    cudaMemcpyAsync(out, x, (size_t)out_size * sizeof(float),
                    cudaMemcpyDeviceToDevice);
}